// round 1
// baseline (speedup 1.0000x reference)
#include <cuda_runtime.h>
#include <cstdint>
#include <math.h>

#define TT 64
#define NB 32
#define CC 128
#define DD 64

// scratch: one 64-bit spike word (over t) per (n,c)
__device__ unsigned long long g_s2bits[NB * CC];

// ---------------------------------------------------------------------------
// Kernel 1: per-(n,c) warp. Jeffress LIF (2 units/lane) + kint dot +
// integrator IF + square model (lanes 0-9), all T steps, emit spike bits.
// ---------------------------------------------------------------------------
__global__ void __launch_bounds__(256) k1_jeffress(
    const float* __restrict__ x,
    const float* __restrict__ w1, const float* __restrict__ b1,
    const float* __restrict__ w2, const float* __restrict__ b2)
{
    const unsigned FULL = 0xFFFFFFFFu;
    const int lane = threadIdx.x & 31;
    const int wg   = (blockIdx.x * blockDim.x + threadIdx.x) >> 5;  // 0..4095
    const int n = wg >> 7;        // wg / CC
    const int c = wg & (CC - 1);  // wg % CC

    // --- pack input spikes into 64-bit words (bit t = x[t]) ----------------
    // x layout: (T, N, 2, C): idx = ((t*NB + n)*2 + ch)*CC + c
    const int base = n * 2 * CC + c;
    const int strideT = NB * 2 * CC;
    unsigned lo0 = __ballot_sync(FULL, x[base + lane * strideT]            != 0.0f);
    unsigned hi0 = __ballot_sync(FULL, x[base + (lane + 32) * strideT]     != 0.0f);
    unsigned lo1 = __ballot_sync(FULL, x[base + CC + lane * strideT]       != 0.0f);
    unsigned hi1 = __ballot_sync(FULL, x[base + CC + (lane + 32) * strideT]!= 0.0f);
    unsigned long long bx0 = (unsigned long long)lo0 | ((unsigned long long)hi0 << 32);
    unsigned long long bx1 = (unsigned long long)lo1 | ((unsigned long long)hi1 << 32);

    // unit j sees x0 delayed by j, x1 delayed by (D-1-j). Pre-shift so that
    // bit 0 after t right-shifts gives the needed sample (zeros pad t<delay).
    const int j0 = lane, j1 = lane + 32;
    unsigned long long a00 = bx0 << j0;
    unsigned long long a01 = bx0 << j1;
    unsigned long long a10 = bx1 << (63 - j0);
    unsigned long long a11 = bx1 << (63 - j1);

    // kint[j] = 1/(1 - exp(-|j-32|/2)), center clamped to |d|=1
    auto kintf = [](int j) {
        int d = j - 32;
        float ad = (d == 0) ? 1.0f : fabsf((float)d);
        return 1.0f / (1.0f - expf(-ad * 0.5f));
    };
    const float k0 = kintf(j0), k1v = kintf(j1);

    float w1l = 0.0f, b1l = 0.0f, w2l = 0.0f;
    if (lane < 10) { w1l = w1[lane]; b1l = b1[lane]; w2l = w2[lane]; }
    const float b2v = b2[0];

    float vj0 = 0.0f, vj1 = 0.0f;        // jeffress LIF potentials
    float vi = 0.0f;                     // integrator IF
    float f1 = 0.0f, v1 = 0.0f;          // square model stage 1
    float f2 = 0.0f, v2 = 0.0f;          // square model stage 2
    unsigned long long s2w = 0ull, tbit = 1ull;

    for (int t = 0; t < TT; ++t) {
        // inputs u in {0,1,2}
        float u0 = (float)(int)((a00 & 1ull) + (a10 & 1ull));
        float u1 = (float)(int)((a01 & 1ull) + (a11 & 1ull));
        a00 >>= 1; a01 >>= 1; a10 >>= 1; a11 >>= 1;

        // LIF: v += (u - v)/20 ; fire at v>=1 ; hard reset
        vj0 += (u0 - vj0) * 0.05f;
        vj1 += (u1 - vj1) * 0.05f;
        bool s0 = (vj0 >= 1.0f), s1 = (vj1 >= 1.0f);
        float zp = (s0 ? k0 : 0.0f) + (s1 ? k1v : 0.0f);
        if (s0) vj0 = 0.0f;
        if (s1) vj1 = 0.0f;

        // dot(spikes, kint) across the 64 units of this (n,c)
        zp += __shfl_xor_sync(FULL, zp, 16);
        zp += __shfl_xor_sync(FULL, zp, 8);
        zp += __shfl_xor_sync(FULL, zp, 4);
        zp += __shfl_xor_sync(FULL, zp, 2);
        zp += __shfl_xor_sync(FULL, zp, 1);

        // integrator IF (replicated on all lanes)
        vi += zp;
        bool si = (vi >= 1.0f);
        if (si) vi = 0.0f;

        // square model: filter -> Linear(1,10) -> IF -> filter -> Linear(10,1) -> IF
        f1 = 0.5f * f1 + (si ? 1.0f : 0.0f);
        v1 += f1 * w1l + b1l;                  // lanes >=10: stays 0
        bool sq1 = (v1 >= 1.0f);
        if (sq1) v1 = 0.0f;
        f2 = 0.5f * f2 + (sq1 ? 1.0f : 0.0f);
        float p = f2 * w2l;                    // lanes >=10 contribute 0
        p += __shfl_xor_sync(FULL, p, 16);
        p += __shfl_xor_sync(FULL, p, 8);
        p += __shfl_xor_sync(FULL, p, 4);
        p += __shfl_xor_sync(FULL, p, 2);
        p += __shfl_xor_sync(FULL, p, 1);
        v2 += p + b2v;
        bool s2 = (v2 >= 1.0f);
        if (s2) { v2 = 0.0f; s2w |= tbit; }
        tbit <<= 1;
    }

    if (lane == 0) g_s2bits[wg] = s2w;
}

// ---------------------------------------------------------------------------
// Kernel 2: per-n block (64 threads). Popcount spike words over c -> linear
// filter of counts -> sum IF -> sqrt model (warp 0, 32-wide). Final q2 dot is
// feedback-free: keep per-lane partials in the serial loop, reduce after.
// ---------------------------------------------------------------------------
__global__ void __launch_bounds__(64) k2_tail(
    const float* __restrict__ sw0, const float* __restrict__ sb0,
    const float* __restrict__ sw1, const float* __restrict__ sb1,
    const float* __restrict__ sw2, const float* __restrict__ sb2,
    float* __restrict__ out)
{
    __shared__ unsigned long long words[CC];
    __shared__ float s2sum[TT];
    __shared__ float sw1s[32 * 32];
    __shared__ float qbuf[TT][33];   // pad to avoid bank conflicts in reduce

    const unsigned FULL = 0xFFFFFFFFu;
    const int n = blockIdx.x;
    const int tid = threadIdx.x;

    words[tid]      = g_s2bits[n * CC + tid];
    words[tid + 64] = g_s2bits[n * CC + tid + 64];
    for (int i = tid; i < 1024; i += 64) sw1s[i] = sw1[i];
    __syncthreads();

    // per-timestep spike count over c (fs filter is linear => count suffices)
    {
        int t = tid;  // 0..63
        int cnt = 0;
        #pragma unroll 8
        for (int c = 0; c < CC; ++c) cnt += (int)((words[c] >> t) & 1ull);
        s2sum[t] = (float)cnt;
    }
    __syncthreads();

    if (tid < 32) {
        const int lane = tid;
        const float sw0l = sw0[lane], sb0l = sb0[lane];
        const float sb1l = sb1[lane], sw2l = sw2[lane];
        const float sb2v = (lane == 0) ? sb2[0] : 0.0f;
        float r[32];
        #pragma unroll
        for (int k = 0; k < 32; ++k) r[k] = sw1s[lane * 32 + k];

        float fsum = 0.0f, vs = 0.0f;
        float q0 = 0.0f, g1 = 0.0f, q1 = 0.0f, g2 = 0.0f, q2p = 0.0f;

        for (int t = 0; t < TT; ++t) {
            // fs filter of counts, sum IF neuron
            fsum = 0.5f * fsum + s2sum[t];
            vs += fsum;
            bool s5 = (vs >= 1.0f);
            if (s5) vs = 0.0f;
            float h = s5 ? 1.0f : 0.0f;

            // sqrt model: q0 uses raw h (g0 state is dead in the reference)
            q0 += h * sw0l + sb0l;
            bool sA = (q0 >= 1.0f);
            if (sA) q0 = 0.0f;
            g1 = 0.5f * g1 + (sA ? 1.0f : 0.0f);

            // q1[i] += sum_k sw1[i,k] * g1[k]  (shuffle-broadcast matvec)
            float a0 = 0.0f, a1 = 0.0f, a2 = 0.0f, a3 = 0.0f;
            #pragma unroll
            for (int k = 0; k < 32; k += 4) {
                a0 += r[k]     * __shfl_sync(FULL, g1, k);
                a1 += r[k + 1] * __shfl_sync(FULL, g1, k + 1);
                a2 += r[k + 2] * __shfl_sync(FULL, g1, k + 2);
                a3 += r[k + 3] * __shfl_sync(FULL, g1, k + 3);
            }
            q1 += (a0 + a1) + (a2 + a3) + sb1l;
            bool sB = (q1 >= 1.0f);
            if (sB) q1 = 0.0f;
            g2 = 0.5f * g2 + (sB ? 1.0f : 0.0f);

            // non-spiking output accumulator: per-lane partial, reduce later
            q2p += g2 * sw2l + sb2v;
            qbuf[t][lane] = q2p;
        }
    }
    __syncthreads();

    // reduce per-lane q2 partials for each t, write out (T,N,1)
    {
        int t = tid;  // 0..63
        float s = 0.0f;
        #pragma unroll
        for (int l = 0; l < 32; ++l) s += qbuf[t][l];
        out[t * NB + n] = s;
    }
}

// ---------------------------------------------------------------------------
extern "C" void kernel_launch(void* const* d_in, const int* in_sizes, int n_in,
                              void* d_out, int out_size)
{
    const float* x   = (const float*)d_in[0];
    const float* w1  = (const float*)d_in[1];
    const float* b1  = (const float*)d_in[2];
    const float* w2  = (const float*)d_in[3];
    const float* b2  = (const float*)d_in[4];
    const float* sw0 = (const float*)d_in[5];
    const float* sb0 = (const float*)d_in[6];
    const float* sw1 = (const float*)d_in[7];
    const float* sb1 = (const float*)d_in[8];
    const float* sw2 = (const float*)d_in[9];
    const float* sb2 = (const float*)d_in[10];
    float* out = (float*)d_out;

    // 4096 warps (one per (n,c)) = 512 blocks x 256 threads
    k1_jeffress<<<512, 256>>>(x, w1, b1, w2, b2);
    // one block per batch element
    k2_tail<<<NB, 64>>>(sw0, sb0, sw1, sb1, sw2, sb2, out);
}

// round 3
// speedup vs baseline: 1.2821x; 1.2821x over previous
#include <cuda_runtime.h>
#include <cstdint>
#include <math.h>

#define TT 64
#define NB 32
#define CC 128
#define DD 64
#define NC (NB * CC)

typedef unsigned long long u64;

// per-(n,c): 64 timestep masks (64 units each) ; spike words for the tail
__device__ u64 g_masks[NC * TT];          // [nc][t]
__device__ u64 g_s2bits[NC];
__device__ float g_klut[8 * 256];         // byte-wise kint masked sums
__device__ float g_w2lut[1024];           // 10-bit w2 masked sums

// ---------------------------------------------------------------------------
// K1: warp per (n,c). Jeffress LIF (2 units/lane) over all T; per-t ballot
// transpose -> 64-bit unit mask per t. Block 0 also builds the global LUTs.
// ---------------------------------------------------------------------------
__global__ void __launch_bounds__(256) k1_lif(
    const float* __restrict__ x, const float* __restrict__ w2)
{
    const unsigned FULL = 0xFFFFFFFFu;
    const int lane = threadIdx.x & 31;
    const int wg   = (blockIdx.x * blockDim.x + threadIdx.x) >> 5;  // nc
    const int n = wg >> 7;
    const int c = wg & (CC - 1);

    if (blockIdx.x == 0) {
        const int tid = threadIdx.x;
        // kint byte LUT (uniform trip counts -> no divergence before ballots)
        #pragma unroll 1
        for (int e = tid; e < 2048; e += 256) {
            int b = e >> 8, m = e & 255;
            float s = 0.0f;
            #pragma unroll
            for (int i = 0; i < 8; ++i)
                if (m & (1 << i)) {
                    int d = (b * 8 + i) - 32;
                    float ad = (d == 0) ? 1.0f : fabsf((float)d);
                    s += 1.0f / (1.0f - expf(-ad * 0.5f));
                }
            g_klut[e] = s;
        }
        #pragma unroll 1
        for (int e = tid; e < 1024; e += 256) {
            float s = 0.0f;
            #pragma unroll
            for (int i = 0; i < 10; ++i)
                if (e & (1 << i)) s += w2[i];
            g_w2lut[e] = s;
        }
    }

    // pack input spikes: bit t of bx = x[t] != 0
    const int base = n * 2 * CC + c;
    const int strideT = NB * 2 * CC;
    unsigned lo0 = __ballot_sync(FULL, x[base + lane * strideT]             != 0.0f);
    unsigned hi0 = __ballot_sync(FULL, x[base + (lane + 32) * strideT]      != 0.0f);
    unsigned lo1 = __ballot_sync(FULL, x[base + CC + lane * strideT]        != 0.0f);
    unsigned hi1 = __ballot_sync(FULL, x[base + CC + (lane + 32) * strideT] != 0.0f);
    u64 bx0 = (u64)lo0 | ((u64)hi0 << 32);
    u64 bx1 = (u64)lo1 | ((u64)hi1 << 32);

    // unit j sees x0 delayed by j, x1 delayed by (D-1-j): pre-shift
    u64 a0 = bx0 << lane;            // unit j0 = lane
    u64 a1 = bx0 << (lane + 32);     // unit j1 = lane + 32
    u64 d0 = bx1 << (63 - lane);
    u64 d1 = bx1 << (31 - lane);

    float vj0 = 0.0f, vj1 = 0.0f;
    u64 keepA = 0ull, keepB = 0ull;

    #pragma unroll
    for (int t = 0; t < TT; ++t) {
        float u0 = (((a0 >> t) & 1ull) ? 1.0f : 0.0f)
                 + (((d0 >> t) & 1ull) ? 1.0f : 0.0f);
        float u1 = (((a1 >> t) & 1ull) ? 1.0f : 0.0f)
                 + (((d1 >> t) & 1ull) ? 1.0f : 0.0f);
        vj0 = fmaf(u0 - vj0, 0.05f, vj0);
        vj1 = fmaf(u1 - vj1, 0.05f, vj1);
        bool s0 = (vj0 >= 1.0f), s1 = (vj1 >= 1.0f);
        unsigned m0 = __ballot_sync(FULL, s0);
        unsigned m1 = __ballot_sync(FULL, s1);
        vj0 = s0 ? 0.0f : vj0;
        vj1 = s1 ? 0.0f : vj1;
        u64 mk = (u64)m0 | ((u64)m1 << 32);
        if (t < 32) { if (lane == t)      keepA = mk; }
        else        { if (lane == t - 32) keepB = mk; }
    }

    g_masks[wg * TT + lane]      = keepA;   // coalesced 256B stores
    g_masks[wg * TT + 32 + lane] = keepB;
}

// ---------------------------------------------------------------------------
// K2: thread per (n,c), 32-thread blocks. zc via byte LUTs, integrator IF,
// 10-unit square model per thread (w2 dot as scalar recurrence via LUT).
// ---------------------------------------------------------------------------
__global__ void __launch_bounds__(32) k2_square(
    const float* __restrict__ w1, const float* __restrict__ b1,
    const float* __restrict__ b2)
{
    __shared__ u64 stage[32 * 65];            // padded rows: 2-way max conflict
    const int tid = threadIdx.x;
    const int nc0 = blockIdx.x * 32;

    #pragma unroll 4
    for (int i = tid; i < 32 * TT; i += 32) {
        int row = i >> 6, t = i & 63;
        stage[row * 65 + t] = g_masks[(nc0 + row) * TT + t];   // coalesced
    }

    float w1r[10], b1r[10];
    #pragma unroll
    for (int i = 0; i < 10; ++i) { w1r[i] = w1[i]; b1r[i] = b1[i]; }
    const float b2v = b2[0];

    __syncwarp();

    const u64* myrow = &stage[tid * 65];
    float vi = 0.0f, f1 = 0.0f, dotp = 0.0f, v2 = 0.0f;
    float v1[10];
    #pragma unroll
    for (int i = 0; i < 10; ++i) v1[i] = 0.0f;
    u64 s2w = 0ull, tbit = 1ull;

    #pragma unroll 4
    for (int t = 0; t < TT; ++t) {
        u64 mk = myrow[t];
        unsigned lo = (unsigned)mk, hi = (unsigned)(mk >> 32);
        float zc = ((g_klut[        (lo      ) & 255] + g_klut[ 256 + ((lo >>  8) & 255)])
                 +  (g_klut[ 512 + ((lo >> 16) & 255)] + g_klut[ 768 + ((lo >> 24)      )]))
                 + ((g_klut[1024 + ((hi      ) & 255)] + g_klut[1280 + ((hi >>  8) & 255)])
                 +  (g_klut[1536 + ((hi >> 16) & 255)] + g_klut[1792 + ((hi >> 24)      )]));

        vi += zc;
        bool si = (vi >= 1.0f);
        vi = si ? 0.0f : vi;

        f1 = fmaf(f1, 0.5f, si ? 1.0f : 0.0f);
        unsigned msk = 0u;
        #pragma unroll
        for (int i = 0; i < 10; ++i) {
            v1[i] = fmaf(f1, w1r[i], v1[i]) + b1r[i];
            bool sq = (v1[i] >= 1.0f);
            v1[i] = sq ? 0.0f : v1[i];
            msk |= sq ? (1u << i) : 0u;
        }
        dotp = fmaf(dotp, 0.5f, g_w2lut[msk]);   // = w2 . f2_t
        v2 += dotp + b2v;
        bool s2 = (v2 >= 1.0f);
        v2 = s2 ? 0.0f : v2;
        s2w |= s2 ? tbit : 0ull;
        tbit <<= 1;
    }

    g_s2bits[nc0 + tid] = s2w;
}

// ---------------------------------------------------------------------------
// K3: per-n block, 128 threads. Pipeline-split tail:
//  P1 spike counts -> P2 serial h/q0 masks -> P3 t-parallel masked matvec ->
//  P4 skinny serial loop -> P5 reduce q2 partials.
// ---------------------------------------------------------------------------
__global__ void __launch_bounds__(128) k3_tail(
    const float* __restrict__ sw0, const float* __restrict__ sb0,
    const float* __restrict__ sw1, const float* __restrict__ sb1,
    const float* __restrict__ sw2, const float* __restrict__ sb2,
    float* __restrict__ out)
{
    __shared__ u64 words[CC];
    __shared__ float sw1s[32 * 33];
    __shared__ int   cnt2[128];
    __shared__ float cntf[TT];
    __shared__ unsigned sa_masks[TT];
    __shared__ float msb[TT][33];
    __shared__ float qbuf[TT][33];

    const unsigned FULL = 0xFFFFFFFFu;
    const int n = blockIdx.x;
    const int tid = threadIdx.x;
    const int lane = tid & 31;
    const int wid = tid >> 5;

    words[tid] = g_s2bits[n * CC + tid];
    #pragma unroll
    for (int i = tid; i < 1024; i += 128) {
        int row = i >> 5, col = i & 31;
        sw1s[row * 33 + col] = sw1[i];
    }
    __syncthreads();

    // P1: spike count over c per timestep (2 threads per t)
    {
        int t = tid >> 1, h = tid & 1;
        int cnt = 0;
        #pragma unroll 8
        for (int cc = 0; cc < 64; ++cc)
            cnt += (int)((words[h * 64 + cc] >> t) & 1ull);
        cnt2[tid] = cnt;
    }
    float r[32];
    #pragma unroll
    for (int k = 0; k < 32; ++k) r[k] = sw1s[lane * 33 + k];
    __syncthreads();
    if (tid < 64) cntf[tid] = (float)(cnt2[2 * tid] + cnt2[2 * tid + 1]);
    __syncthreads();

    // P2: serial h + q0 stage -> sA masks (~20 cyc/t chain)
    if (wid == 0) {
        const float sw0l = sw0[lane], sb0l = sb0[lane];
        float fsum = 0.0f, vs = 0.0f, q0 = 0.0f;
        #pragma unroll 4
        for (int t = 0; t < TT; ++t) {
            fsum = fmaf(fsum, 0.5f, cntf[t]);
            vs += fsum;
            bool s5 = (vs >= 1.0f);
            float hf = s5 ? 1.0f : 0.0f;
            vs = s5 ? 0.0f : vs;
            q0 += fmaf(hf, sw0l, sb0l);
            bool pA = (q0 >= 1.0f);
            unsigned m = __ballot_sync(FULL, pA);
            q0 = pA ? 0.0f : q0;
            if (lane == 0) sa_masks[t] = m;
        }
    }
    __syncthreads();

    // P3: t-parallel masked row sums (16 timesteps per warp)
    {
        const int t0 = wid * 16;
        for (int t = t0; t < t0 + 16; ++t) {
            unsigned m = sa_masks[t];
            float a0 = 0.0f, a1 = 0.0f, a2 = 0.0f, a3 = 0.0f;
            #pragma unroll
            for (int k = 0; k < 32; k += 4) {
                if (m & (1u << k))       a0 += r[k];
                if (m & (1u << (k + 1))) a1 += r[k + 1];
                if (m & (1u << (k + 2))) a2 += r[k + 2];
                if (m & (1u << (k + 3))) a3 += r[k + 3];
            }
            msb[t][lane] = (a0 + a1) + (a2 + a3);
        }
    }
    __syncthreads();

    // P4: skinny serial loop, no shuffles on the chain
    if (wid == 0) {
        const float sb1l = sb1[lane], sw2l = sw2[lane];
        const float sb2v = (lane == 0) ? sb2[0] : 0.0f;
        float dot = 0.0f, q1 = 0.0f, g2 = 0.0f, q2p = 0.0f;
        #pragma unroll 4
        for (int t = 0; t < TT; ++t) {
            dot = fmaf(dot, 0.5f, msb[t][lane]);   // = sw1 . g1_t
            q1 = q1 + dot + sb1l;
            bool pB = (q1 >= 1.0f);
            float sBf = pB ? 1.0f : 0.0f;
            q1 = pB ? 0.0f : q1;
            g2 = fmaf(g2, 0.5f, sBf);
            q2p = fmaf(g2, sw2l, q2p) + sb2v;
            qbuf[t][lane] = q2p;
        }
    }
    __syncthreads();

    // P5: reduce per-lane q2 partials -> out (T,N,1)
    if (tid < 64) {
        int t = tid;
        float s = 0.0f;
        #pragma unroll
        for (int l = 0; l < 32; ++l) s += qbuf[t][l];
        out[t * NB + n] = s;
    }
}

// ---------------------------------------------------------------------------
extern "C" void kernel_launch(void* const* d_in, const int* in_sizes, int n_in,
                              void* d_out, int out_size)
{
    const float* x   = (const float*)d_in[0];
    const float* w1  = (const float*)d_in[1];
    const float* b1  = (const float*)d_in[2];
    const float* w2  = (const float*)d_in[3];
    const float* b2  = (const float*)d_in[4];
    const float* sw0 = (const float*)d_in[5];
    const float* sb0 = (const float*)d_in[6];
    const float* sw1 = (const float*)d_in[7];
    const float* sb1 = (const float*)d_in[8];
    const float* sw2 = (const float*)d_in[9];
    const float* sb2 = (const float*)d_in[10];
    float* out = (float*)d_out;

    k1_lif<<<512, 256>>>(x, w2);
    k2_square<<<CC, 32>>>(w1, b1, b2);
    k3_tail<<<NB, 128>>>(sw0, sb0, sw1, sb1, sw2, sb2, out);
}

// round 4
// speedup vs baseline: 1.3575x; 1.0588x over previous
#include <cuda_runtime.h>
#include <cstdint>
#include <math.h>

#define TT 64
#define NB 32
#define CC 128
#define DD 64
#define NC (NB * CC)

typedef unsigned long long u64;

// per-(n,c): 64 timestep masks (64 units each) ; spike words for the tail
__device__ u64 g_masks[NC * TT];          // [nc][t], contiguous per nc
__device__ u64 g_s2bits[NC];
__device__ float g_klut[8 * 256];         // byte-wise kint masked sums
__device__ float g_w2lut[1024];           // 10-bit w2 masked sums

// ---------------------------------------------------------------------------
// K1: warp per (n,c). Jeffress LIF (2 units/lane) over all T; per-t ballot ->
// uniform 64-bit mask, staged in smem by lane 0, coalesced store at the end.
// Block 0 also builds the global LUTs (from a tiny kint_s table, few expf).
// ---------------------------------------------------------------------------
__global__ void __launch_bounds__(256) k1_lif(
    const float* __restrict__ x, const float* __restrict__ w2)
{
    __shared__ u64 sm_masks[8 * TT];      // 4KB: [warp][t]
    __shared__ float kint_s[64];

    const unsigned FULL = 0xFFFFFFFFu;
    const int tid  = threadIdx.x;
    const int lane = tid & 31;
    const int wid  = tid >> 5;
    const int wg   = (blockIdx.x * blockDim.x + tid) >> 5;  // nc
    const int n = wg >> 7;
    const int c = wg & (CC - 1);

    if (blockIdx.x == 0) {
        if (tid < 64) {
            int d = tid - 32;
            float ad = (d == 0) ? 1.0f : fabsf((float)d);
            kint_s[tid] = 1.0f / (1.0f - expf(-ad * 0.5f));
        }
        __syncthreads();
        #pragma unroll 1
        for (int e = tid; e < 2048; e += 256) {
            int b = e >> 8, m = e & 255;
            float s = 0.0f;
            #pragma unroll
            for (int i = 0; i < 8; ++i)
                if (m & (1 << i)) s += kint_s[b * 8 + i];
            g_klut[e] = s;
        }
        #pragma unroll 1
        for (int e = tid; e < 1024; e += 256) {
            float s = 0.0f;
            #pragma unroll
            for (int i = 0; i < 10; ++i)
                if (e & (1 << i)) s += w2[i];
            g_w2lut[e] = s;
        }
    }

    // pack input spikes: bit t of bx = x[t] != 0
    const int base = n * 2 * CC + c;
    const int strideT = NB * 2 * CC;
    unsigned lo0 = __ballot_sync(FULL, x[base + lane * strideT]             != 0.0f);
    unsigned hi0 = __ballot_sync(FULL, x[base + (lane + 32) * strideT]      != 0.0f);
    unsigned lo1 = __ballot_sync(FULL, x[base + CC + lane * strideT]        != 0.0f);
    unsigned hi1 = __ballot_sync(FULL, x[base + CC + (lane + 32) * strideT] != 0.0f);
    u64 bx0 = (u64)lo0 | ((u64)hi0 << 32);
    u64 bx1 = (u64)lo1 | ((u64)hi1 << 32);

    // unit j sees x0 delayed by j, x1 delayed by (D-1-j): pre-shift
    u64 a0 = bx0 << lane;            // unit j0 = lane
    u64 a1 = bx0 << (lane + 32);     // unit j1 = lane + 32
    u64 d0 = bx1 << (63 - lane);
    u64 d1 = bx1 << (31 - lane);

    float vj0 = 0.0f, vj1 = 0.0f;
    const bool store_lane = (lane == 0);
    u64* myrow = &sm_masks[wid * TT];

    #pragma unroll
    for (int t = 0; t < TT; ++t) {
        float u0 = (((a0 >> t) & 1ull) ? 1.0f : 0.0f)
                 + (((d0 >> t) & 1ull) ? 1.0f : 0.0f);
        float u1 = (((a1 >> t) & 1ull) ? 1.0f : 0.0f)
                 + (((d1 >> t) & 1ull) ? 1.0f : 0.0f);
        vj0 = fmaf(u0 - vj0, 0.05f, vj0);
        vj1 = fmaf(u1 - vj1, 0.05f, vj1);
        bool s0 = (vj0 >= 1.0f), s1 = (vj1 >= 1.0f);
        unsigned m0 = __ballot_sync(FULL, s0);
        unsigned m1 = __ballot_sync(FULL, s1);
        vj0 = s0 ? 0.0f : vj0;
        vj1 = s1 ? 0.0f : vj1;
        if (store_lane) myrow[t] = (u64)m0 | ((u64)m1 << 32);
    }

    __syncthreads();
    // coalesced copy: block's 8 warps cover nc = blockIdx*8..+7, 512 words
    const int gbase = blockIdx.x * 8 * TT;
    g_masks[gbase + tid]       = sm_masks[tid];
    g_masks[gbase + 256 + tid] = sm_masks[256 + tid];
}

// ---------------------------------------------------------------------------
// K2: thread per (n,c), 32-thread blocks. LUTs copied to shared once; zc via
// byte LUTs, integrator IF, 10-unit square model per thread (w2 dot as scalar
// recurrence via LUT).
// ---------------------------------------------------------------------------
__global__ void __launch_bounds__(32) k2_square(
    const float* __restrict__ w1, const float* __restrict__ b1,
    const float* __restrict__ b2)
{
    __shared__ u64 stage[32 * 65];            // padded rows
    __shared__ float klut_s[2048];
    __shared__ float w2lut_s[1024];
    const int tid = threadIdx.x;
    const int nc0 = blockIdx.x * 32;

    #pragma unroll 4
    for (int i = tid; i < 32 * TT; i += 32) {
        int row = i >> 6, t = i & 63;
        stage[row * 65 + t] = g_masks[(nc0 + row) * TT + t];   // coalesced
    }
    #pragma unroll 8
    for (int i = tid; i < 2048; i += 32) klut_s[i] = g_klut[i];
    #pragma unroll 8
    for (int i = tid; i < 1024; i += 32) w2lut_s[i] = g_w2lut[i];

    float w1r[10], b1r[10];
    #pragma unroll
    for (int i = 0; i < 10; ++i) { w1r[i] = w1[i]; b1r[i] = b1[i]; }
    const float b2v = b2[0];

    __syncwarp();

    const u64* myrow = &stage[tid * 65];
    float vi = 0.0f, f1 = 0.0f, dotp = 0.0f, v2 = 0.0f;
    float v1[10];
    #pragma unroll
    for (int i = 0; i < 10; ++i) v1[i] = 0.0f;
    u64 s2w = 0ull, tbit = 1ull;

    #pragma unroll 8
    for (int t = 0; t < TT; ++t) {
        u64 mk = myrow[t];
        unsigned lo = (unsigned)mk, hi = (unsigned)(mk >> 32);
        float zc = ((klut_s[        (lo      ) & 255] + klut_s[ 256 + ((lo >>  8) & 255)])
                 +  (klut_s[ 512 + ((lo >> 16) & 255)] + klut_s[ 768 + ((lo >> 24)      )]))
                 + ((klut_s[1024 + ((hi      ) & 255)] + klut_s[1280 + ((hi >>  8) & 255)])
                 +  (klut_s[1536 + ((hi >> 16) & 255)] + klut_s[1792 + ((hi >> 24)      )]));

        vi += zc;
        bool si = (vi >= 1.0f);
        vi = si ? 0.0f : vi;

        f1 = fmaf(f1, 0.5f, si ? 1.0f : 0.0f);
        unsigned msk = 0u;
        #pragma unroll
        for (int i = 0; i < 10; ++i) {
            v1[i] = fmaf(f1, w1r[i], v1[i]) + b1r[i];
            bool sq = (v1[i] >= 1.0f);
            v1[i] = sq ? 0.0f : v1[i];
            msk |= sq ? (1u << i) : 0u;
        }
        dotp = fmaf(dotp, 0.5f, w2lut_s[msk]);   // = w2 . f2_t
        v2 += dotp + b2v;
        bool s2 = (v2 >= 1.0f);
        v2 = s2 ? 0.0f : v2;
        s2w |= s2 ? tbit : 0ull;
        tbit <<= 1;
    }

    g_s2bits[nc0 + tid] = s2w;
}

// ---------------------------------------------------------------------------
// K3: per-n block, 128 threads. Pipeline-split tail (unchanged).
// ---------------------------------------------------------------------------
__global__ void __launch_bounds__(128) k3_tail(
    const float* __restrict__ sw0, const float* __restrict__ sb0,
    const float* __restrict__ sw1, const float* __restrict__ sb1,
    const float* __restrict__ sw2, const float* __restrict__ sb2,
    float* __restrict__ out)
{
    __shared__ u64 words[CC];
    __shared__ float sw1s[32 * 33];
    __shared__ int   cnt2[128];
    __shared__ float cntf[TT];
    __shared__ unsigned sa_masks[TT];
    __shared__ float msb[TT][33];
    __shared__ float qbuf[TT][33];

    const unsigned FULL = 0xFFFFFFFFu;
    const int n = blockIdx.x;
    const int tid = threadIdx.x;
    const int lane = tid & 31;
    const int wid = tid >> 5;

    words[tid] = g_s2bits[n * CC + tid];
    #pragma unroll
    for (int i = tid; i < 1024; i += 128) {
        int row = i >> 5, col = i & 31;
        sw1s[row * 33 + col] = sw1[i];
    }
    __syncthreads();

    // P1: spike count over c per timestep (2 threads per t)
    {
        int t = tid >> 1, h = tid & 1;
        int cnt = 0;
        #pragma unroll 8
        for (int cc = 0; cc < 64; ++cc)
            cnt += (int)((words[h * 64 + cc] >> t) & 1ull);
        cnt2[tid] = cnt;
    }
    float r[32];
    #pragma unroll
    for (int k = 0; k < 32; ++k) r[k] = sw1s[lane * 33 + k];
    __syncthreads();
    if (tid < 64) cntf[tid] = (float)(cnt2[2 * tid] + cnt2[2 * tid + 1]);
    __syncthreads();

    // P2: serial h + q0 stage -> sA masks
    if (wid == 0) {
        const float sw0l = sw0[lane], sb0l = sb0[lane];
        float fsum = 0.0f, vs = 0.0f, q0 = 0.0f;
        #pragma unroll 4
        for (int t = 0; t < TT; ++t) {
            fsum = fmaf(fsum, 0.5f, cntf[t]);
            vs += fsum;
            bool s5 = (vs >= 1.0f);
            float hf = s5 ? 1.0f : 0.0f;
            vs = s5 ? 0.0f : vs;
            q0 += fmaf(hf, sw0l, sb0l);
            bool pA = (q0 >= 1.0f);
            unsigned m = __ballot_sync(FULL, pA);
            q0 = pA ? 0.0f : q0;
            if (lane == 0) sa_masks[t] = m;
        }
    }
    __syncthreads();

    // P3: t-parallel masked row sums (16 timesteps per warp)
    {
        const int t0 = wid * 16;
        for (int t = t0; t < t0 + 16; ++t) {
            unsigned m = sa_masks[t];
            float a0 = 0.0f, a1 = 0.0f, a2 = 0.0f, a3 = 0.0f;
            #pragma unroll
            for (int k = 0; k < 32; k += 4) {
                if (m & (1u << k))       a0 += r[k];
                if (m & (1u << (k + 1))) a1 += r[k + 1];
                if (m & (1u << (k + 2))) a2 += r[k + 2];
                if (m & (1u << (k + 3))) a3 += r[k + 3];
            }
            msb[t][lane] = (a0 + a1) + (a2 + a3);
        }
    }
    __syncthreads();

    // P4: skinny serial loop, no shuffles on the chain
    if (wid == 0) {
        const float sb1l = sb1[lane], sw2l = sw2[lane];
        const float sb2v = (lane == 0) ? sb2[0] : 0.0f;
        float dot = 0.0f, q1 = 0.0f, g2 = 0.0f, q2p = 0.0f;
        #pragma unroll 4
        for (int t = 0; t < TT; ++t) {
            dot = fmaf(dot, 0.5f, msb[t][lane]);   // = sw1 . g1_t
            q1 = q1 + dot + sb1l;
            bool pB = (q1 >= 1.0f);
            float sBf = pB ? 1.0f : 0.0f;
            q1 = pB ? 0.0f : q1;
            g2 = fmaf(g2, 0.5f, sBf);
            q2p = fmaf(g2, sw2l, q2p) + sb2v;
            qbuf[t][lane] = q2p;
        }
    }
    __syncthreads();

    // P5: reduce per-lane q2 partials -> out (T,N,1)
    if (tid < 64) {
        int t = tid;
        float s = 0.0f;
        #pragma unroll
        for (int l = 0; l < 32; ++l) s += qbuf[t][l];
        out[t * NB + n] = s;
    }
}

// ---------------------------------------------------------------------------
extern "C" void kernel_launch(void* const* d_in, const int* in_sizes, int n_in,
                              void* d_out, int out_size)
{
    const float* x   = (const float*)d_in[0];
    const float* w1  = (const float*)d_in[1];
    const float* b1  = (const float*)d_in[2];
    const float* w2  = (const float*)d_in[3];
    const float* b2  = (const float*)d_in[4];
    const float* sw0 = (const float*)d_in[5];
    const float* sb0 = (const float*)d_in[6];
    const float* sw1 = (const float*)d_in[7];
    const float* sb1 = (const float*)d_in[8];
    const float* sw2 = (const float*)d_in[9];
    const float* sb2 = (const float*)d_in[10];
    float* out = (float*)d_out;

    k1_lif<<<512, 256>>>(x, w2);
    k2_square<<<CC, 32>>>(w1, b1, b2);
    k3_tail<<<NB, 128>>>(sw0, sb0, sw1, sb1, sw2, sb2, out);
}

// round 5
// speedup vs baseline: 1.8767x; 1.3825x over previous
#include <cuda_runtime.h>
#include <cstdint>
#include <math.h>

#define TT 64
#define NB 32
#define CC 128
#define DD 64
#define NC (NB * CC)

typedef unsigned long long u64;

// per-(n,c): 64-bit integrator-spike word over t (si = any jeffress spike)
__device__ u64 g_si[NC];

// ---------------------------------------------------------------------------
// K1: warp per (n,c). Jeffress LIF (2 units/lane) over all T.
// Exact shortcut: every kint > 1 and the integrator IF hard-resets, so the
// integrator spike si_t == (any unit spiked at t)  ->  one VOTE.ANY per t.
// ---------------------------------------------------------------------------
__global__ void __launch_bounds__(256) k1_lif(const float* __restrict__ x)
{
    const unsigned FULL = 0xFFFFFFFFu;
    const int tid  = threadIdx.x;
    const int lane = tid & 31;
    const int wg   = (blockIdx.x * blockDim.x + tid) >> 5;  // nc
    const int n = wg >> 7;
    const int c = wg & (CC - 1);

    // pack input spikes: bit t of bx = x[t] != 0
    const int base = n * 2 * CC + c;
    const int strideT = NB * 2 * CC;
    unsigned lo0 = __ballot_sync(FULL, x[base + lane * strideT]             != 0.0f);
    unsigned hi0 = __ballot_sync(FULL, x[base + (lane + 32) * strideT]      != 0.0f);
    unsigned lo1 = __ballot_sync(FULL, x[base + CC + lane * strideT]        != 0.0f);
    unsigned hi1 = __ballot_sync(FULL, x[base + CC + (lane + 32) * strideT] != 0.0f);
    u64 bx0 = (u64)lo0 | ((u64)hi0 << 32);
    u64 bx1 = (u64)lo1 | ((u64)hi1 << 32);

    // unit j sees x0 delayed by j, x1 delayed by (D-1-j): pre-shift
    u64 a0 = bx0 << lane;            // unit j0 = lane
    u64 a1 = bx0 << (lane + 32);     // unit j1 = lane + 32
    u64 d0 = bx1 << (63 - lane);
    u64 d1 = bx1 << (31 - lane);

    float vj0 = 0.0f, vj1 = 0.0f;
    u64 siw = 0ull;

    #pragma unroll
    for (int t = 0; t < TT; ++t) {
        float u0 = (((a0 >> t) & 1ull) ? 1.0f : 0.0f)
                 + (((d0 >> t) & 1ull) ? 1.0f : 0.0f);
        float u1 = (((a1 >> t) & 1ull) ? 1.0f : 0.0f)
                 + (((d1 >> t) & 1ull) ? 1.0f : 0.0f);
        vj0 = fmaf(u0 - vj0, 0.05f, vj0);
        vj1 = fmaf(u1 - vj1, 0.05f, vj1);
        bool s0 = (vj0 >= 1.0f), s1 = (vj1 >= 1.0f);
        bool any = __any_sync(FULL, s0 | s1);
        vj0 = s0 ? 0.0f : vj0;
        vj1 = s1 ? 0.0f : vj1;
        if (any) siw |= (1ull << t);
    }

    if (lane == 0) g_si[wg] = siw;
}

// ---------------------------------------------------------------------------
// K2K3: one block per n, 128 threads (thread = channel).
// Phase S (square model, per channel serial): f1 -> 10 IF units -> w2-dot
// recurrence via 1024-entry LUT -> v2 IF -> s2 spike word (into smem).
// Then the pipeline-split tail: P1 counts -> P2 serial masks -> P3 t-parallel
// matvec -> P4 skinny serial -> P5 reduce.
// ---------------------------------------------------------------------------
__global__ void __launch_bounds__(128) k2k3(
    const float* __restrict__ w1, const float* __restrict__ b1,
    const float* __restrict__ w2, const float* __restrict__ b2,
    const float* __restrict__ sw0, const float* __restrict__ sb0,
    const float* __restrict__ sw1, const float* __restrict__ sb1,
    const float* __restrict__ sw2, const float* __restrict__ sb2,
    float* __restrict__ out)
{
    __shared__ u64 words[CC];
    __shared__ float w2lut_s[1024];
    __shared__ float sw1s[32 * 33];
    __shared__ int   cnt2[128];
    __shared__ float cntf[TT];
    __shared__ unsigned sa_masks[TT];
    __shared__ float msb[TT][33];
    __shared__ float qbuf[TT][33];

    const unsigned FULL = 0xFFFFFFFFu;
    const int n = blockIdx.x;
    const int tid = threadIdx.x;
    const int lane = tid & 31;
    const int wid = tid >> 5;

    // weights + biases
    float w1r[10], b1r[10];
    #pragma unroll
    for (int i = 0; i < 10; ++i) { w1r[i] = w1[i]; b1r[i] = b1[i]; }
    const float b2v = b2[0];
    float babs = fabsf(b2v);
    #pragma unroll
    for (int i = 0; i < 10; ++i) babs += fabsf(b1r[i]);
    const bool bias_zero = (babs == 0.0f);

    // build w2 masked-sum LUT (1024 entries, 8 per thread)
    #pragma unroll
    for (int e = tid; e < 1024; e += 128) {
        float s = 0.0f;
        #pragma unroll
        for (int i = 0; i < 10; ++i)
            if (e & (1 << i)) s += w2[i];
        w2lut_s[e] = s;
    }
    #pragma unroll
    for (int i = tid; i < 1024; i += 128) {
        int row = i >> 5, col = i & 31;
        sw1s[row * 33 + col] = sw1[i];
    }

    const u64 siw = g_si[n * CC + tid];    // coalesced
    __syncthreads();

    // ---- Phase S: square model per channel ----
    {
        float f1 = 0.0f, dotp = 0.0f, v2 = 0.0f;
        float v1[10];
        #pragma unroll
        for (int i = 0; i < 10; ++i) v1[i] = 0.0f;
        u64 s2w = 0ull;

        if (bias_zero) {
            // exact: x + 0.0f == x for all values arising here
            #pragma unroll 8
            for (int t = 0; t < TT; ++t) {
                float sif = ((siw >> t) & 1ull) ? 1.0f : 0.0f;
                f1 = fmaf(f1, 0.5f, sif);
                unsigned msk = 0u;
                #pragma unroll
                for (int i = 0; i < 10; ++i) {
                    v1[i] = fmaf(f1, w1r[i], v1[i]);
                    bool sq = (v1[i] >= 1.0f);
                    v1[i] = sq ? 0.0f : v1[i];
                    msk |= sq ? (1u << i) : 0u;
                }
                dotp = fmaf(dotp, 0.5f, w2lut_s[msk]);   // = w2 . f2_t
                v2 += dotp;
                bool s2 = (v2 >= 1.0f);
                v2 = s2 ? 0.0f : v2;
                s2w |= s2 ? (1ull << t) : 0ull;
            }
        } else {
            #pragma unroll 8
            for (int t = 0; t < TT; ++t) {
                float sif = ((siw >> t) & 1ull) ? 1.0f : 0.0f;
                f1 = fmaf(f1, 0.5f, sif);
                unsigned msk = 0u;
                #pragma unroll
                for (int i = 0; i < 10; ++i) {
                    v1[i] = fmaf(f1, w1r[i], v1[i]) + b1r[i];
                    bool sq = (v1[i] >= 1.0f);
                    v1[i] = sq ? 0.0f : v1[i];
                    msk |= sq ? (1u << i) : 0u;
                }
                dotp = fmaf(dotp, 0.5f, w2lut_s[msk]);
                v2 += dotp + b2v;
                bool s2 = (v2 >= 1.0f);
                v2 = s2 ? 0.0f : v2;
                s2w |= s2 ? (1ull << t) : 0ull;
            }
        }
        words[tid] = s2w;
    }
    __syncthreads();

    // ---- P1: spike count over c per timestep (2 threads per t) ----
    {
        int t = tid >> 1, h = tid & 1;
        int cnt = 0;
        #pragma unroll 8
        for (int cc = 0; cc < 64; ++cc)
            cnt += (int)((words[h * 64 + cc] >> t) & 1ull);
        cnt2[tid] = cnt;
    }
    float r[32];
    #pragma unroll
    for (int k = 0; k < 32; ++k) r[k] = sw1s[lane * 33 + k];
    __syncthreads();
    if (tid < 64) cntf[tid] = (float)(cnt2[2 * tid] + cnt2[2 * tid + 1]);
    __syncthreads();

    // ---- P2: serial h + q0 stage -> sA masks ----
    if (wid == 0) {
        const float sw0l = sw0[lane], sb0l = sb0[lane];
        float fsum = 0.0f, vs = 0.0f, q0 = 0.0f;
        #pragma unroll 4
        for (int t = 0; t < TT; ++t) {
            fsum = fmaf(fsum, 0.5f, cntf[t]);
            vs += fsum;
            bool s5 = (vs >= 1.0f);
            float hf = s5 ? 1.0f : 0.0f;
            vs = s5 ? 0.0f : vs;
            q0 += fmaf(hf, sw0l, sb0l);
            bool pA = (q0 >= 1.0f);
            unsigned m = __ballot_sync(FULL, pA);
            q0 = pA ? 0.0f : q0;
            if (lane == 0) sa_masks[t] = m;
        }
    }
    __syncthreads();

    // ---- P3: t-parallel masked row sums (16 timesteps per warp) ----
    {
        const int t0 = wid * 16;
        for (int t = t0; t < t0 + 16; ++t) {
            unsigned m = sa_masks[t];
            float a0 = 0.0f, a1 = 0.0f, a2 = 0.0f, a3 = 0.0f;
            #pragma unroll
            for (int k = 0; k < 32; k += 4) {
                if (m & (1u << k))       a0 += r[k];
                if (m & (1u << (k + 1))) a1 += r[k + 1];
                if (m & (1u << (k + 2))) a2 += r[k + 2];
                if (m & (1u << (k + 3))) a3 += r[k + 3];
            }
            msb[t][lane] = (a0 + a1) + (a2 + a3);
        }
    }
    __syncthreads();

    // ---- P4: skinny serial loop, no shuffles on the chain ----
    if (wid == 0) {
        const float sb1l = sb1[lane], sw2l = sw2[lane];
        const float sb2v = (lane == 0) ? sb2[0] : 0.0f;
        float dot = 0.0f, q1 = 0.0f, g2 = 0.0f, q2p = 0.0f;
        #pragma unroll 4
        for (int t = 0; t < TT; ++t) {
            dot = fmaf(dot, 0.5f, msb[t][lane]);   // = sw1 . g1_t
            q1 = q1 + dot + sb1l;
            bool pB = (q1 >= 1.0f);
            float sBf = pB ? 1.0f : 0.0f;
            q1 = pB ? 0.0f : q1;
            g2 = fmaf(g2, 0.5f, sBf);
            q2p = fmaf(g2, sw2l, q2p) + sb2v;
            qbuf[t][lane] = q2p;
        }
    }
    __syncthreads();

    // ---- P5: reduce per-lane q2 partials -> out (T,N,1) ----
    if (tid < 64) {
        int t = tid;
        float s = 0.0f;
        #pragma unroll
        for (int l = 0; l < 32; ++l) s += qbuf[t][l];
        out[t * NB + n] = s;
    }
}

// ---------------------------------------------------------------------------
extern "C" void kernel_launch(void* const* d_in, const int* in_sizes, int n_in,
                              void* d_out, int out_size)
{
    const float* x   = (const float*)d_in[0];
    const float* w1  = (const float*)d_in[1];
    const float* b1  = (const float*)d_in[2];
    const float* w2  = (const float*)d_in[3];
    const float* b2  = (const float*)d_in[4];
    const float* sw0 = (const float*)d_in[5];
    const float* sb0 = (const float*)d_in[6];
    const float* sw1 = (const float*)d_in[7];
    const float* sb1 = (const float*)d_in[8];
    const float* sw2 = (const float*)d_in[9];
    const float* sb2 = (const float*)d_in[10];
    float* out = (float*)d_out;

    k1_lif<<<512, 256>>>(x);
    k2k3<<<NB, 128>>>(w1, b1, w2, b2, sw0, sb0, sw1, sb1, sw2, sb2, out);
}

// round 7
// speedup vs baseline: 2.0123x; 1.0722x over previous
#include <cuda_runtime.h>
#include <cstdint>
#include <math.h>

#define TT 64
#define NB 32
#define CC 128
#define DD 64
#define NC (NB * CC)

typedef unsigned long long u64;

// per-(n,c): 64-bit integrator-spike word over t (si = any jeffress spike)
__device__ u64 g_si[NC];

#define BAR_ARRIVE(id, cnt) asm volatile("bar.arrive %0, %1;" :: "r"(id), "r"(cnt) : "memory")
#define BAR_SYNC(id, cnt)   asm volatile("bar.sync %0, %1;"   :: "r"(id), "r"(cnt) : "memory")

// ---------------------------------------------------------------------------
// K1: warp per (n,c). Jeffress LIF (2 units/lane) over all T.
// Exact shortcut: every kint > 1 and the integrator IF hard-resets, so the
// integrator spike si_t == (any unit spiked at t)  ->  one VOTE.ANY per t.
// ---------------------------------------------------------------------------
__global__ void __launch_bounds__(256) k1_lif(const float* __restrict__ x)
{
    const unsigned FULL = 0xFFFFFFFFu;
    const int tid  = threadIdx.x;
    const int lane = tid & 31;
    const int wg   = (blockIdx.x * blockDim.x + tid) >> 5;  // nc
    const int n = wg >> 7;
    const int c = wg & (CC - 1);

    // pack input spikes: bit t of bx = x[t] != 0
    const int base = n * 2 * CC + c;
    const int strideT = NB * 2 * CC;
    unsigned lo0 = __ballot_sync(FULL, x[base + lane * strideT]             != 0.0f);
    unsigned hi0 = __ballot_sync(FULL, x[base + (lane + 32) * strideT]      != 0.0f);
    unsigned lo1 = __ballot_sync(FULL, x[base + CC + lane * strideT]        != 0.0f);
    unsigned hi1 = __ballot_sync(FULL, x[base + CC + (lane + 32) * strideT] != 0.0f);
    u64 bx0 = (u64)lo0 | ((u64)hi0 << 32);
    u64 bx1 = (u64)lo1 | ((u64)hi1 << 32);

    // unit j sees x0 delayed by j, x1 delayed by (D-1-j): pre-shift
    u64 a0 = bx0 << lane;            // unit j0 = lane
    u64 a1 = bx0 << (lane + 32);     // unit j1 = lane + 32
    u64 d0 = bx1 << (63 - lane);
    u64 d1 = bx1 << (31 - lane);

    float vj0 = 0.0f, vj1 = 0.0f;
    u64 siw = 0ull;

    #pragma unroll
    for (int t = 0; t < TT; ++t) {
        float u0 = (((a0 >> t) & 1ull) ? 1.0f : 0.0f)
                 + (((d0 >> t) & 1ull) ? 1.0f : 0.0f);
        float u1 = (((a1 >> t) & 1ull) ? 1.0f : 0.0f)
                 + (((d1 >> t) & 1ull) ? 1.0f : 0.0f);
        vj0 = fmaf(u0 - vj0, 0.05f, vj0);
        vj1 = fmaf(u1 - vj1, 0.05f, vj1);
        bool s0 = (vj0 >= 1.0f), s1 = (vj1 >= 1.0f);
        bool any = __any_sync(FULL, s0 | s1);
        vj0 = s0 ? 0.0f : vj0;
        vj1 = s1 ? 0.0f : vj1;
        siw |= any ? (1ull << t) : 0ull;
    }

    if (lane == 0) g_si[wg] = siw;
}

// ---------------------------------------------------------------------------
// K2K3: one block per n, 256 threads, warp-specialized chunk pipeline
// (chunk = 16 timesteps, 4 chunks). Barrier audit:
//   id 1+c : producers (warps 0-3) 128 arrive + warp 4 32 sync  = 160
//   id 5+c : warp 4 32 arrive + warps 5,6 64 sync               = 96
//   id 9+c : warps 5,6 64 arrive + warp 7 32 sync               = 96
// Each id used exactly once; __syncthreads (id 0) only after all drained.
// ---------------------------------------------------------------------------
__global__ void __launch_bounds__(256) k2k3(
    const float* __restrict__ w1, const float* __restrict__ b1,
    const float* __restrict__ w2, const float* __restrict__ b2,
    const float* __restrict__ sw0, const float* __restrict__ sb0,
    const float* __restrict__ sw1, const float* __restrict__ sb1,
    const float* __restrict__ sw2, const float* __restrict__ sb2,
    float* __restrict__ out)
{
    __shared__ unsigned chunk_bits[4][CC];
    __shared__ float cnt_s[4][16];
    __shared__ unsigned sa_masks[TT];
    __shared__ float sw1s[32 * 33];
    __shared__ float msb[TT][33];
    __shared__ float qbuf[TT][33];

    const unsigned FULL = 0xFFFFFFFFu;
    const int n = blockIdx.x;
    const int tid = threadIdx.x;
    const int lane = tid & 31;
    const int wid = tid >> 5;

    #pragma unroll
    for (int i = tid; i < 1024; i += 256) {
        int row = i >> 5, col = i & 31;
        sw1s[row * 33 + col] = sw1[i];
    }
    __syncthreads();

    if (wid < 4) {
        // ---- Phase S producers: thread = channel (tid 0..127) ----
        float w1r[10], b1r[10], w2r[10];
        #pragma unroll
        for (int i = 0; i < 10; ++i) { w1r[i] = w1[i]; b1r[i] = b1[i]; w2r[i] = w2[i]; }
        const float b2v = b2[0];
        float babs = fabsf(b2v);
        #pragma unroll
        for (int i = 0; i < 10; ++i) babs += fabsf(b1r[i]);
        const bool bias_zero = (babs == 0.0f);   // block-uniform

        const u64 siw = g_si[n * CC + tid];

        float f1 = 0.0f, dotp = 0.0f, v2 = 0.0f;
        float v1[10];
        #pragma unroll
        for (int i = 0; i < 10; ++i) v1[i] = 0.0f;

        if (bias_zero) {
            // exact: x + 0.0f == x for every value arising here; the dsum
            // select-adds reproduce the ascending-i summation order exactly.
            #pragma unroll 1
            for (int cch = 0; cch < 4; ++cch) {
                unsigned sb16 = (unsigned)(siw >> (16 * cch));
                unsigned cb = 0u;
                #pragma unroll
                for (int tt = 0; tt < 16; ++tt) {
                    float sif = ((sb16 >> tt) & 1u) ? 1.0f : 0.0f;
                    f1 = fmaf(f1, 0.5f, sif);
                    float dsum = 0.0f;
                    #pragma unroll
                    for (int i = 0; i < 10; ++i) {
                        v1[i] = fmaf(f1, w1r[i], v1[i]);
                        bool sq = (v1[i] >= 1.0f);
                        v1[i] = sq ? 0.0f : v1[i];
                        dsum += sq ? w2r[i] : 0.0f;
                    }
                    dotp = fmaf(dotp, 0.5f, dsum);      // = w2 . f2_t
                    v2 += dotp;
                    bool s2 = (v2 >= 1.0f);
                    v2 = s2 ? 0.0f : v2;
                    cb |= s2 ? (1u << tt) : 0u;
                }
                chunk_bits[cch][tid] = cb;
                BAR_ARRIVE(1 + cch, 160);
            }
        } else {
            #pragma unroll 1
            for (int cch = 0; cch < 4; ++cch) {
                unsigned sb16 = (unsigned)(siw >> (16 * cch));
                unsigned cb = 0u;
                #pragma unroll
                for (int tt = 0; tt < 16; ++tt) {
                    float sif = ((sb16 >> tt) & 1u) ? 1.0f : 0.0f;
                    f1 = fmaf(f1, 0.5f, sif);
                    float dsum = 0.0f;
                    #pragma unroll
                    for (int i = 0; i < 10; ++i) {
                        v1[i] = fmaf(f1, w1r[i], v1[i]) + b1r[i];
                        bool sq = (v1[i] >= 1.0f);
                        v1[i] = sq ? 0.0f : v1[i];
                        dsum += sq ? w2r[i] : 0.0f;
                    }
                    dotp = fmaf(dotp, 0.5f, dsum);
                    v2 += dotp + b2v;
                    bool s2 = (v2 >= 1.0f);
                    v2 = s2 ? 0.0f : v2;
                    cb |= s2 ? (1u << tt) : 0u;
                }
                chunk_bits[cch][tid] = cb;
                BAR_ARRIVE(1 + cch, 160);
            }
        }
    } else if (wid == 4) {
        // ---- count + serial h/q0 chain ----
        const float sw0l = sw0[lane], sb0l = sb0[lane];
        float fsum = 0.0f, vs = 0.0f, q0 = 0.0f;
        const int myt = lane & 15;
        #pragma unroll 1
        for (int cch = 0; cch < 4; ++cch) {
            BAR_SYNC(1 + cch, 160);
            int cnt = 0;
            #pragma unroll 8
            for (int ch = 0; ch < CC; ++ch)
                cnt += (int)((chunk_bits[cch][ch] >> myt) & 1u);
            if (lane < 16) cnt_s[cch][lane] = (float)cnt;
            __syncwarp();
            #pragma unroll
            for (int tt = 0; tt < 16; ++tt) {
                int t = 16 * cch + tt;
                fsum = fmaf(fsum, 0.5f, cnt_s[cch][tt]);
                vs += fsum;
                bool s5 = (vs >= 1.0f);
                float hf = s5 ? 1.0f : 0.0f;
                vs = s5 ? 0.0f : vs;
                q0 += fmaf(hf, sw0l, sb0l);
                bool pA = (q0 >= 1.0f);
                unsigned m = __ballot_sync(FULL, pA);
                q0 = pA ? 0.0f : q0;
                if (lane == 0) sa_masks[t] = m;
            }
            BAR_ARRIVE(5 + cch, 96);
        }
    } else if (wid < 7) {
        // ---- t-parallel masked matvec, 8 timesteps per warp per chunk ----
        float r[32];
        #pragma unroll
        for (int k = 0; k < 32; ++k) r[k] = sw1s[lane * 33 + k];
        const int toff = (wid - 5) * 8;
        #pragma unroll 1
        for (int cch = 0; cch < 4; ++cch) {
            BAR_SYNC(5 + cch, 96);
            const int t0 = 16 * cch + toff;
            #pragma unroll
            for (int t = t0; t < t0 + 8; ++t) {
                unsigned m = sa_masks[t];
                float a0 = 0.0f, a1 = 0.0f, a2 = 0.0f, a3 = 0.0f;
                #pragma unroll
                for (int k = 0; k < 32; k += 4) {
                    if (m & (1u << k))       a0 += r[k];
                    if (m & (1u << (k + 1))) a1 += r[k + 1];
                    if (m & (1u << (k + 2))) a2 += r[k + 2];
                    if (m & (1u << (k + 3))) a3 += r[k + 3];
                }
                msb[t][lane] = (a0 + a1) + (a2 + a3);
            }
            BAR_ARRIVE(9 + cch, 96);
        }
    } else {
        // ---- serial dot/q1/g2/q2 chain ----
        const float sb1l = sb1[lane], sw2l = sw2[lane];
        const float sb2v = (lane == 0) ? sb2[0] : 0.0f;
        float dot = 0.0f, q1 = 0.0f, g2 = 0.0f, q2p = 0.0f;
        #pragma unroll 1
        for (int cch = 0; cch < 4; ++cch) {
            BAR_SYNC(9 + cch, 96);
            #pragma unroll
            for (int tt = 0; tt < 16; ++tt) {
                int t = 16 * cch + tt;
                dot = fmaf(dot, 0.5f, msb[t][lane]);   // = sw1 . g1_t
                q1 = q1 + dot + sb1l;
                bool pB = (q1 >= 1.0f);
                float sBf = pB ? 1.0f : 0.0f;
                q1 = pB ? 0.0f : q1;
                g2 = fmaf(g2, 0.5f, sBf);
                q2p = fmaf(g2, sw2l, q2p) + sb2v;
                qbuf[t][lane] = q2p;
            }
        }
    }
    __syncthreads();

    // ---- reduce per-lane q2 partials -> out (T,N,1) ----
    if (tid < 64) {
        int t = tid;
        float s = 0.0f;
        #pragma unroll
        for (int l = 0; l < 32; ++l) s += qbuf[t][l];
        out[t * NB + n] = s;
    }
}

// ---------------------------------------------------------------------------
extern "C" void kernel_launch(void* const* d_in, const int* in_sizes, int n_in,
                              void* d_out, int out_size)
{
    const float* x   = (const float*)d_in[0];
    const float* w1  = (const float*)d_in[1];
    const float* b1  = (const float*)d_in[2];
    const float* w2  = (const float*)d_in[3];
    const float* b2  = (const float*)d_in[4];
    const float* sw0 = (const float*)d_in[5];
    const float* sb0 = (const float*)d_in[6];
    const float* sw1 = (const float*)d_in[7];
    const float* sb1 = (const float*)d_in[8];
    const float* sw2 = (const float*)d_in[9];
    const float* sb2 = (const float*)d_in[10];
    float* out = (float*)d_out;

    k1_lif<<<512, 256>>>(x);
    k2k3<<<NB, 256>>>(w1, b1, w2, b2, sw0, sb0, sw1, sb1, sw2, sb2, out);
}